// round 1
// baseline (speedup 1.0000x reference)
#include <cuda_runtime.h>

// LSTM_584115552367: B=65536 independent LSTMs, D=H=17, T=50, SLB=30.
// Strategy: 1 thread owns 2 batch elements packed as f32x2 (fma.rn.f32x2 = FFMA2),
// weights staged in SMEM pre-duplicated (w,w) and d-paired so LDS.128 feeds 2 FFMA2.
// Fully register-resident state; no syncs after weight staging.

#define BSZ   65536
#define TLEN  50
#define DDIM  17
#define SLBC  30
#define GN    68          // 4*D gates
#define NP    9           // padded d-pairs: 18/2
#define TPB   128
#define TOUT  (TLEN - SLBC)   // 20

typedef unsigned long long u64;

__device__ __forceinline__ u64 pack2(float lo, float hi) {
    u64 r; asm("mov.b64 %0, {%1, %2};" : "=l"(r) : "f"(lo), "f"(hi)); return r;
}
__device__ __forceinline__ void unpack2(u64 v, float &lo, float &hi) {
    asm("mov.b64 {%0, %1}, %2;" : "=f"(lo), "=f"(hi) : "l"(v));
}
__device__ __forceinline__ void fma2a(u64 &acc, u64 a, u64 b) {
    asm("fma.rn.f32x2 %0, %1, %2, %0;" : "+l"(acc) : "l"(a), "l"(b));
}
__device__ __forceinline__ u64 fma2(u64 a, u64 b, u64 c) {
    u64 r; asm("fma.rn.f32x2 %0, %1, %2, %3;" : "=l"(r) : "l"(a), "l"(b), "l"(c)); return r;
}
__device__ __forceinline__ u64 mul2(u64 a, u64 b) {
    u64 r; asm("mul.rn.f32x2 %0, %1, %2;" : "=l"(r) : "l"(a), "l"(b)); return r;
}

__device__ __forceinline__ float ex2f(float x) {
    float r; asm("ex2.approx.f32 %0, %1;" : "=f"(r) : "f"(x)); return r;
}
__device__ __forceinline__ float rcpf(float x) {
    float r; asm("rcp.approx.f32 %0, %1;" : "=f"(r) : "f"(x)); return r;
}
// sigmoid(x) = 1 / (1 + 2^(-x*log2e)); safe at both extremes (rcp(inf)=0).
__device__ __forceinline__ float sigm(float x) {
    return rcpf(1.0f + ex2f(-1.4426950408889634f * x));
}
// tanh(x) = sign(x) * (1-e)/(1+e), e = 2^(-2|x|*log2e); e<=1 so no inf/NaN.
__device__ __forceinline__ float tanhx(float x) {
    float ax = fabsf(x);
    float e  = ex2f(-2.8853900817779268f * ax);
    float r  = (1.0f - e) * rcpf(1.0f + e);
    return copysignf(r, x);
}
__device__ __forceinline__ u64 sigm2(u64 v) { float a, b; unpack2(v, a, b); return pack2(sigm(a),  sigm(b)); }
__device__ __forceinline__ u64 tanh2(u64 v) { float a, b; unpack2(v, a, b); return pack2(tanhx(a), tanhx(b)); }

__global__ void __launch_bounds__(TPB) lstm_kernel(
    const float* __restrict__ x,     // [B, T, D]
    const float* __restrict__ Wih,   // [4D, D]
    const float* __restrict__ Whh,   // [4D, D]
    const float* __restrict__ bih,   // [4D]
    const float* __restrict__ bhh,   // [4D]
    const float* __restrict__ Wlin,  // [D, D]
    const float* __restrict__ blin,  // [D]
    const float* __restrict__ mih,   // [4D, D]
    const float* __restrict__ mhh,   // [4D, D]
    float* __restrict__ out)         // [B, TOUT, D]
{
    // SMEM weights: duplicated pairs, d padded to 18 (pad weight = 0).
    // sW*[q*NP + p] = { (w[q][2p], w[q][2p]), (w[q][2p+1], w[q][2p+1]) }
    __shared__ ulonglong2 sWih[GN * NP];
    __shared__ ulonglong2 sWhh[GN * NP];
    __shared__ ulonglong2 sWlin[DDIM * NP];
    __shared__ u64 sBg[GN];
    __shared__ u64 sBlin[DDIM];

    for (int idx = threadIdx.x; idx < GN * NP; idx += TPB) {
        int q = idx / NP, p = idx % NP;
        int d0 = 2 * p, d1 = 2 * p + 1;
        float wi0 = Wih[q * DDIM + d0] * mih[q * DDIM + d0];
        float wi1 = (d1 < DDIM) ? Wih[q * DDIM + d1] * mih[q * DDIM + d1] : 0.0f;
        float wh0 = Whh[q * DDIM + d0] * mhh[q * DDIM + d0];
        float wh1 = (d1 < DDIM) ? Whh[q * DDIM + d1] * mhh[q * DDIM + d1] : 0.0f;
        ulonglong2 a; a.x = pack2(wi0, wi0); a.y = pack2(wi1, wi1); sWih[idx] = a;
        ulonglong2 b; b.x = pack2(wh0, wh0); b.y = pack2(wh1, wh1); sWhh[idx] = b;
    }
    for (int idx = threadIdx.x; idx < DDIM * NP; idx += TPB) {
        int cc = idx / NP, p = idx % NP;
        int d0 = 2 * p, d1 = 2 * p + 1;
        float w0 = Wlin[cc * DDIM + d0];
        float w1 = (d1 < DDIM) ? Wlin[cc * DDIM + d1] : 0.0f;
        ulonglong2 a; a.x = pack2(w0, w0); a.y = pack2(w1, w1); sWlin[idx] = a;
    }
    if (threadIdx.x < GN)   { float b = bih[threadIdx.x] + bhh[threadIdx.x]; sBg[threadIdx.x]   = pack2(b, b); }
    if (threadIdx.x < DDIM) { float b = blin[threadIdx.x];                   sBlin[threadIdx.x] = pack2(b, b); }
    __syncthreads();

    const int pairIdx = blockIdx.x * TPB + threadIdx.x;   // 0 .. 32767
    const long b0 = (long)pairIdx * 2;
    const float* __restrict__ xb0 = x + b0 * (TLEN * DDIM);
    const float* __restrict__ xb1 = xb0 + (TLEN * DDIM);
    float* __restrict__ ob0 = out + b0 * (TOUT * DDIM);
    float* __restrict__ ob1 = ob0 + (TOUT * DDIM);

    // Register-resident state (f32x2 pairs); pad slot [17] stays zero forever.
    u64 xi[18], h[18], c[DDIM], hn[DDIM];
#pragma unroll
    for (int i = 0; i < 18; i++) { xi[i] = 0ull; h[i] = 0ull; }
#pragma unroll
    for (int i = 0; i < DDIM; i++) { c[i] = 0ull; }

    for (int t = 0; t < TLEN; t++) {
        if (t < SLBC) {
            const float* p0 = xb0 + t * DDIM;
            const float* p1 = xb1 + t * DDIM;
#pragma unroll
            for (int d = 0; d < DDIM; d++) xi[d] = pack2(p0[d], p1[d]);
        }

#pragma unroll
        for (int j = 0; j < DDIM; j++) {
            u64 ai = sBg[j], af = sBg[17 + j], ag = sBg[34 + j], ao = sBg[51 + j];
#pragma unroll
            for (int p = 0; p < NP; p++) {
                u64 x0 = xi[2 * p], x1 = xi[2 * p + 1];
                ulonglong2 wi = sWih[j * NP + p];
                ulonglong2 wf = sWih[(17 + j) * NP + p];
                ulonglong2 wg = sWih[(34 + j) * NP + p];
                ulonglong2 wo = sWih[(51 + j) * NP + p];
                fma2a(ai, x0, wi.x); fma2a(ai, x1, wi.y);
                fma2a(af, x0, wf.x); fma2a(af, x1, wf.y);
                fma2a(ag, x0, wg.x); fma2a(ag, x1, wg.y);
                fma2a(ao, x0, wo.x); fma2a(ao, x1, wo.y);
            }
#pragma unroll
            for (int p = 0; p < NP; p++) {
                u64 h0 = h[2 * p], h1 = h[2 * p + 1];
                ulonglong2 wi = sWhh[j * NP + p];
                ulonglong2 wf = sWhh[(17 + j) * NP + p];
                ulonglong2 wg = sWhh[(34 + j) * NP + p];
                ulonglong2 wo = sWhh[(51 + j) * NP + p];
                fma2a(ai, h0, wi.x); fma2a(ai, h1, wi.y);
                fma2a(af, h0, wf.x); fma2a(af, h1, wf.y);
                fma2a(ag, h0, wg.x); fma2a(ag, h1, wg.y);
                fma2a(ao, h0, wo.x); fma2a(ao, h1, wo.y);
            }
            u64 si = sigm2(ai);
            u64 sf = sigm2(af);
            u64 tg = tanh2(ag);
            u64 so = sigm2(ao);
            u64 cn = fma2(sf, c[j], mul2(si, tg));   // c' = sig(f)*c + sig(i)*tanh(g)
            c[j]  = cn;
            hn[j] = mul2(so, tanh2(cn));             // h' = sig(o)*tanh(c')
        }
#pragma unroll
        for (int j = 0; j < DDIM; j++) h[j] = hn[j];

        if (t >= SLBC - 1) {
            // out = h' @ Wlin^T + b_lin; written straight into xi (feedback input).
#pragma unroll
            for (int cc = 0; cc < DDIM; cc++) {
                u64 acc = sBlin[cc];
#pragma unroll
                for (int p = 0; p < NP; p++) {
                    ulonglong2 w = sWlin[cc * NP + p];
                    fma2a(acc, h[2 * p], w.x);
                    fma2a(acc, h[2 * p + 1], w.y);
                }
                xi[cc] = acc;
            }
            if (t >= SLBC) {
                int tp = t - SLBC;
#pragma unroll
                for (int cc = 0; cc < DDIM; cc++) {
                    float lo, hi; unpack2(xi[cc], lo, hi);
                    ob0[tp * DDIM + cc] = lo;
                    ob1[tp * DDIM + cc] = hi;
                }
            }
        }
    }
}

extern "C" void kernel_launch(void* const* d_in, const int* in_sizes, int n_in,
                              void* d_out, int out_size) {
    const float* x    = (const float*)d_in[0];
    const float* Wih  = (const float*)d_in[1];
    const float* Whh  = (const float*)d_in[2];
    const float* bih  = (const float*)d_in[3];
    const float* bhh  = (const float*)d_in[4];
    const float* Wlin = (const float*)d_in[5];
    const float* blin = (const float*)d_in[6];
    const float* mih  = (const float*)d_in[7];
    const float* mhh  = (const float*)d_in[8];
    float* out = (float*)d_out;

    dim3 grid(BSZ / (2 * TPB));   // 256 CTAs
    dim3 block(TPB);
    lstm_kernel<<<grid, block>>>(x, Wih, Whh, bih, bhh, Wlin, blin, mih, mhh, out);
}

// round 3
// speedup vs baseline: 1.0771x; 1.0771x over previous
#include <cuda_runtime.h>

// LSTM_584115552367: B=65536 independent LSTMs, D=H=17, T=50, SLB=30.
// R2: 1 element/thread, f32x2 SIMD along the d-dimension (no weight duplication).
// 2048 warps (2x R1) for issue-latency hiding; state ~110 regs; SMEM ~12KB.

#define BSZ   65536
#define TLEN  50
#define DDIM  17
#define SLBC  30
#define NP    9            // padded d-pairs (18/2)
#define TPB   64
#define TOUT  (TLEN - SLBC)

typedef unsigned long long u64;

__device__ __forceinline__ u64 pack2(float lo, float hi) {
    u64 r; asm("mov.b64 %0, {%1, %2};" : "=l"(r) : "f"(lo), "f"(hi)); return r;
}
__device__ __forceinline__ void unpack2(u64 v, float &lo, float &hi) {
    asm("mov.b64 {%0, %1}, %2;" : "=f"(lo), "=f"(hi) : "l"(v));
}
__device__ __forceinline__ void fma2a(u64 &acc, u64 a, u64 b) {
    asm("fma.rn.f32x2 %0, %1, %2, %0;" : "+l"(acc) : "l"(a), "l"(b));
}
__device__ __forceinline__ float hadd2(u64 v) {
    float a, b; unpack2(v, a, b); return a + b;
}

__device__ __forceinline__ float ex2f(float x) {
    float r; asm("ex2.approx.f32 %0, %1;" : "=f"(r) : "f"(x)); return r;
}
__device__ __forceinline__ float rcpf(float x) {
    float r; asm("rcp.approx.f32 %0, %1;" : "=f"(r) : "f"(x)); return r;
}
// sigmoid(x) = 1 / (1 + 2^(-x*log2e)); safe at both extremes (rcp(inf)=0).
__device__ __forceinline__ float sigm(float x) {
    return rcpf(1.0f + ex2f(-1.4426950408889634f * x));
}
// tanh(x) = sign(x)*(1-e)/(1+e), e = 2^(-2|x|*log2e); e<=1, no inf/NaN.
__device__ __forceinline__ float tanhx(float x) {
    float ax = fabsf(x);
    float e  = ex2f(-2.8853900817779268f * ax);
    float r  = (1.0f - e) * rcpf(1.0f + e);
    return copysignf(r, x);
}

__global__ void __launch_bounds__(TPB, 7) lstm_kernel(
    const float* __restrict__ x,     // [B, T, D]
    const float* __restrict__ Wih,   // [4D, D]
    const float* __restrict__ Whh,   // [4D, D]
    const float* __restrict__ bih,   // [4D]
    const float* __restrict__ bhh,   // [4D]
    const float* __restrict__ Wlin,  // [D, D]
    const float* __restrict__ blin,  // [D]
    const float* __restrict__ mih,   // [4D, D]
    const float* __restrict__ mhh,   // [4D, D]
    float* __restrict__ out)         // [B, TOUT, D]
{
    // Gate weights: sWq[j][p][q], q=0: ih(i,f) pairs; q=1: ih(g,o); q=2: hh(i,f); q=3: hh(g,o)
    // Each ulonglong2 = two u64 d-pairs: ( (w[gA][2p],w[gA][2p+1]), (w[gB][2p],w[gB][2p+1]) )
    __shared__ ulonglong2 sWq[DDIM * NP * 4];
    __shared__ ulonglong2 sB[DDIM * 2];        // per j: {(bi,0),(bf,0)}, {(bg,0),(bo,0)}
    __shared__ u64 sLin[DDIM * NP];            // Wlin d-pairs
    __shared__ u64 sBlin[DDIM];                // (blin, 0)

    for (int idx = threadIdx.x; idx < DDIM * NP * 4; idx += TPB) {
        int j = idx / 36, r = idx % 36, p = r / 4, q = r % 4;
        const float* W = (q < 2) ? Wih : Whh;
        const float* M = (q < 2) ? mih : mhh;
        int gA = (q & 1) ? (34 + j) : j;
        int gB = (q & 1) ? (51 + j) : (17 + j);
        int d0 = 2 * p, d1 = 2 * p + 1;
        float a0 = W[gA * DDIM + d0] * M[gA * DDIM + d0];
        float a1 = (d1 < DDIM) ? W[gA * DDIM + d1] * M[gA * DDIM + d1] : 0.0f;
        float b0 = W[gB * DDIM + d0] * M[gB * DDIM + d0];
        float b1 = (d1 < DDIM) ? W[gB * DDIM + d1] * M[gB * DDIM + d1] : 0.0f;
        ulonglong2 v; v.x = pack2(a0, a1); v.y = pack2(b0, b1);
        sWq[idx] = v;
    }
    for (int idx = threadIdx.x; idx < DDIM * NP; idx += TPB) {
        int cc = idx / NP, p = idx % NP;
        int d0 = 2 * p, d1 = 2 * p + 1;
        float w0 = Wlin[cc * DDIM + d0];
        float w1 = (d1 < DDIM) ? Wlin[cc * DDIM + d1] : 0.0f;
        sLin[idx] = pack2(w0, w1);
    }
    if (threadIdx.x < DDIM) {
        int j = threadIdx.x;
        ulonglong2 v0, v1;
        v0.x = pack2(bih[j]      + bhh[j],      0.0f);
        v0.y = pack2(bih[17 + j] + bhh[17 + j], 0.0f);
        v1.x = pack2(bih[34 + j] + bhh[34 + j], 0.0f);
        v1.y = pack2(bih[51 + j] + bhh[51 + j], 0.0f);
        sB[2 * j] = v0; sB[2 * j + 1] = v1;
        sBlin[j] = pack2(blin[j], 0.0f);
    }
    __syncthreads();

    const int bi = blockIdx.x * TPB + threadIdx.x;       // element index 0..65535
    const float* __restrict__ xb = x + (long)bi * (TLEN * DDIM);
    float* __restrict__ ob = out + (long)bi * (TOUT * DDIM);

    u64 xi[NP], h[NP];
    float c[DDIM];
#pragma unroll
    for (int p = 0; p < NP; p++) { xi[p] = 0ull; h[p] = 0ull; }
#pragma unroll
    for (int j = 0; j < DDIM; j++) c[j] = 0.0f;

#pragma unroll 1
    for (int t = 0; t < TLEN; t++) {
        if (t < SLBC) {
            const float* px = xb + t * DDIM;
#pragma unroll
            for (int p = 0; p < 8; p++) xi[p] = pack2(px[2 * p], px[2 * p + 1]);
            xi[8] = pack2(px[16], 0.0f);
        }

        float hn[DDIM];
#pragma unroll
        for (int j = 0; j < DDIM; j++) {
            ulonglong2 b0 = sB[2 * j], b1 = sB[2 * j + 1];
            u64 ai = b0.x, af = b0.y, ag = b1.x, ao = b1.y;
#pragma unroll
            for (int p = 0; p < NP; p++) {
                ulonglong2 w0 = sWq[(j * NP + p) * 4 + 0];
                ulonglong2 w1 = sWq[(j * NP + p) * 4 + 1];
                ulonglong2 w2 = sWq[(j * NP + p) * 4 + 2];
                ulonglong2 w3 = sWq[(j * NP + p) * 4 + 3];
                fma2a(ai, xi[p], w0.x); fma2a(af, xi[p], w0.y);
                fma2a(ag, xi[p], w1.x); fma2a(ao, xi[p], w1.y);
                fma2a(ai, h[p],  w2.x); fma2a(af, h[p],  w2.y);
                fma2a(ag, h[p],  w3.x); fma2a(ao, h[p],  w3.y);
            }
            float gi = hadd2(ai), gf = hadd2(af), gg = hadd2(ag), go = hadd2(ao);
            float si = sigm(gi), sf = sigm(gf), tg = tanhx(gg), so = sigm(go);
            float cn = fmaf(sf, c[j], si * tg);
            c[j]  = cn;
            hn[j] = so * tanhx(cn);
        }
#pragma unroll
        for (int p = 0; p < 8; p++) h[p] = pack2(hn[2 * p], hn[2 * p + 1]);
        h[8] = pack2(hn[16], 0.0f);

        if (t >= SLBC - 1) {
            float o[DDIM];
#pragma unroll
            for (int cc = 0; cc < DDIM; cc++) {
                u64 acc = sBlin[cc];
#pragma unroll
                for (int p = 0; p < NP; p++) fma2a(acc, h[p], sLin[cc * NP + p]);
                o[cc] = hadd2(acc);
            }
            if (t >= SLBC) {
                int tp = t - SLBC;
#pragma unroll
                for (int cc = 0; cc < DDIM; cc++) ob[tp * DDIM + cc] = o[cc];
            }
            // Feedback input for next step.
#pragma unroll
            for (int p = 0; p < 8; p++) xi[p] = pack2(o[2 * p], o[2 * p + 1]);
            xi[8] = pack2(o[16], 0.0f);
        }
    }
}

extern "C" void kernel_launch(void* const* d_in, const int* in_sizes, int n_in,
                              void* d_out, int out_size) {
    const float* x    = (const float*)d_in[0];
    const float* Wih  = (const float*)d_in[1];
    const float* Whh  = (const float*)d_in[2];
    const float* bih  = (const float*)d_in[3];
    const float* bhh  = (const float*)d_in[4];
    const float* Wlin = (const float*)d_in[5];
    const float* blin = (const float*)d_in[6];
    const float* mih  = (const float*)d_in[7];
    const float* mhh  = (const float*)d_in[8];
    float* out = (float*)d_out;

    dim3 grid(BSZ / TPB);   // 1024 CTAs of 64 threads -> 2048 warps
    dim3 block(TPB);
    lstm_kernel<<<grid, block>>>(x, Wih, Whh, bih, bhh, Wlin, blin, mih, mhh, out);
}